// round 5
// baseline (speedup 1.0000x reference)
#include <cuda_runtime.h>
#include <stdint.h>

#define BB 2
#define NN 2048
#define TK 8
#define NF 64
#define NNODES (BB*NN)
#define NE (NNODES*TK)

// ---------------- packed-fp32 (FFMA2) helpers ----------------
#define FMA2(acc, a, b) \
    asm("fma.rn.f32x2 %0, %1, %2, %0;" : "+l"(acc) : "l"(a), "l"(b))
#define ADD2(acc, a) \
    asm("add.rn.f32x2 %0, %0, %1;" : "+l"(acc) : "l"(a))
#define DUP2(d, v) \
    asm("mov.b64 %0, {%1, %1};" : "=l"(d) : "f"(v))
#define PACK2(d, lo, hi) \
    asm("mov.b64 %0, {%1, %2};" : "=l"(d) : "f"(lo), "f"(hi))
#define UNPK2(lo, hi, v) \
    asm("mov.b64 {%0, %1}, %2;" : "=f"(lo), "=f"(hi) : "l"(v))

// ---------------- device scratch (no allocations allowed) ----------------
__device__ unsigned char g_mask[NNODES];
__device__ unsigned char g_tmask[NNODES];
__device__ int   g_send[NE];          // sender idx within batch, -1 = invalid
__device__ int   g_cnt[NNODES];       // # valid edges per receiver (prefix)
__device__ float g_A[NE*NF];          // rel_enc @ rp_w[0:64] + rp_b (hoisted)
__device__ float g_q[NNODES*NF];      // pp_w[0:64]^T p_enc + pp_b
__device__ float g_UV[NNODES*128];    // per-step: [U | V] = effin @ [Wr | Ws]
__device__ float g_eff0[NNODES*NF];
__device__ float g_eff1[NNODES*NF];

// ---------------- K0: normalize masks (runtime dtype detection) -------------
__device__ __forceinline__ unsigned char mask_elem(const unsigned char* p, int i) {
    unsigned w0 = *(const unsigned*)p;
    if (w0 == 0x01010101u)            return p[i] != 0;                    // u8/bool
    if (w0 == 0x3f800000u)            return ((const float*)p)[i] != 0.f;  // f32
    /* default int32 */               return ((const int*)p)[i] != 0;      // i32
}
__global__ __launch_bounds__(256) void k_masks(
    const unsigned char* __restrict__ mask_raw,
    const unsigned char* __restrict__ tmask_raw)
{
    int i = blockIdx.x*256 + threadIdx.x;
    if (i < NNODES) {
        g_mask[i]  = mask_elem(mask_raw, i);
        g_tmask[i] = mask_elem(tmask_raw, i);
    }
}

// ---------------- K1: edge construction (8-NN with threshold) ----------------
__global__ __launch_bounds__(256) void k_edges(
    const float* __restrict__ states)
{
    __shared__ float s_st[NN*3];
    __shared__ unsigned char s_m[NN];
    int b  = blockIdx.x / (NN/8);
    int i0 = (blockIdx.x % (NN/8)) * 8;
    const float* stb = states + (size_t)b*NN*3;
    for (int t = threadIdx.x; t < NN*3; t += 256) s_st[t] = stb[t];
    for (int t = threadIdx.x; t < NN;   t += 256) s_m[t]  = g_mask[b*NN + t];
    __syncthreads();

    const float TH2 = 0.12f * 0.12f;

    int w = threadIdx.x >> 5, lane = threadIdx.x & 31;
    int i = i0 + w;
    int node = b*NN + i;
    bool recv_ok = (g_mask[node] != 0) && (g_tmask[node] == 0);

    unsigned long long keys[TK];
#pragma unroll
    for (int k = 0; k < TK; k++) keys[k] = ~0ULL;

    if (recv_ok) {
        float xi = s_st[i*3+0], yi = s_st[i*3+1], zi = s_st[i*3+2];
        unsigned long long curmax = ~0ULL; int maxslot = 0;
        for (int j = lane; j < NN; j += 32) {
            float dx = xi - s_st[j*3+0];
            float dy = yi - s_st[j*3+1];
            float dz = zi - s_st[j*3+2];
            float d2 = fmaf(dx, dx, fmaf(dy, dy, dz*dz));
            if (!s_m[j]) d2 = 1e10f;
            unsigned long long key =
                ((unsigned long long)__float_as_uint(d2) << 32) | (unsigned)j;
            if (key < curmax) {
                keys[maxslot] = key;
                curmax = keys[0]; maxslot = 0;
#pragma unroll
                for (int k = 1; k < TK; k++)
                    if (keys[k] > curmax) { curmax = keys[k]; maxslot = k; }
            }
        }
    }

    int cnt = 0;
#pragma unroll 1
    for (int r = 0; r < TK; r++) {
        unsigned long long mymin = keys[0]; int mslot = 0;
#pragma unroll
        for (int k = 1; k < TK; k++)
            if (keys[k] < mymin) { mymin = keys[k]; mslot = k; }
        unsigned long long v = mymin;
#pragma unroll
        for (int off = 16; off; off >>= 1) {
            unsigned long long o = __shfl_down_sync(0xffffffffu, v, off);
            if (o < v) v = o;
        }
        v = __shfl_sync(0xffffffffu, v, 0);
        if (v == mymin && v != ~0ULL) keys[mslot] = ~0ULL;
        if (lane == 0) {
            float d2 = __uint_as_float((unsigned)(v >> 32));
            int j = (int)(v & 0xffffffffULL);
            bool valid = (v != ~0ULL) && (d2 < TH2);
            g_send[node*TK + r] = valid ? j : -1;
            cnt += valid ? 1 : 0;
        }
    }
    if (lane == 0) g_cnt[node] = cnt;
}

// ---------------- K2: particle encoder + hoisted pp_w top-half ----------------
__global__ __launch_bounds__(256) void k_penc(
    const float* __restrict__ s_delta, const float* __restrict__ a_cur,
    const float* __restrict__ pe_w1, const float* __restrict__ pe_b1,
    const float* __restrict__ pe_w2, const float* __restrict__ pe_b2,
    const float* __restrict__ pp_w,  const float* __restrict__ pp_b)
{
    __shared__ float w1[12*NF], w2[NF*NF], wq[NF*NF];
    __shared__ float b1[NF], b2[NF], bq[NF];
    __shared__ float pin[4][12];
    __shared__ float hb[4][NF];
    for (int t = threadIdx.x; t < 12*NF; t += 256) w1[t] = pe_w1[t];
    for (int t = threadIdx.x; t < NF*NF; t += 256) w2[t] = pe_w2[t];
    for (int t = threadIdx.x; t < NF*NF; t += 256) wq[t] = pp_w[t]; // rows 0..63
    if (threadIdx.x < NF) {
        b1[threadIdx.x] = pe_b1[threadIdx.x];
        b2[threadIdx.x] = pe_b2[threadIdx.x];
        bq[threadIdx.x] = pp_b[threadIdx.x];
    }
    __syncthreads();

    int g = threadIdx.x >> 6;
    int c = threadIdx.x & 63;
    for (int it = 0; it < 4; ++it) {
        int node = blockIdx.x*16 + it*4 + g;
        int b = node / NN, n = node % NN;
        if (c < 12)
            pin[g][c] = (c < 9) ? s_delta[((size_t)b*9 + c)*NN + n]
                                : a_cur[b*NN + n];
        __syncthreads();
        float acc = b1[c];
#pragma unroll
        for (int r = 0; r < 12; r++) acc = fmaf(pin[g][r], w1[r*NF+c], acc);
        hb[g][c] = fmaxf(acc, 0.f);
        __syncthreads();
        acc = b2[c];
#pragma unroll 16
        for (int r = 0; r < NF; r++) acc = fmaf(hb[g][r], w2[r*NF+c], acc);
        float pe = fmaxf(acc, 0.f);
        g_eff0[(size_t)node*NF + c] = pe;
        __syncthreads();
        hb[g][c] = pe;
        __syncthreads();
        acc = bq[c];
#pragma unroll 16
        for (int r = 0; r < NF; r++) acc = fmaf(hb[g][r], wq[r*NF+c], acc);
        g_q[(size_t)node*NF + c] = acc;
        __syncthreads();
    }
}

// ---------------- K3: relation encoder, edge-per-thread, FFMA2, fused relA ---
__global__ __launch_bounds__(128) void k_rel(
    const float* __restrict__ states, const float* __restrict__ a_cur,
    const float* __restrict__ re_w1, const float* __restrict__ re_b1,
    const float* __restrict__ re_w2, const float* __restrict__ re_b2,
    const float* __restrict__ re_w3, const float* __restrict__ re_b3,
    const float* __restrict__ rp_w,  const float* __restrict__ rp_b)
{
    extern __shared__ float dsm[];
    float* sw1 = dsm;              // 5*64
    float* swb = dsm + 320;        // 3 big mats: 3*4096
    float* sb1 = dsm + 320 + 3*4096;
    float* sbb = sb1 + 64;

    for (int t = threadIdx.x; t < 5*NF; t += 128) sw1[t] = re_w1[t];
    for (int t = threadIdx.x; t < NF*NF; t += 128) {
        swb[t]        = re_w2[t];
        swb[4096 + t] = re_w3[t];
        swb[8192 + t] = rp_w[t];     // rows 0..63 of rp_w
    }
    if (threadIdx.x < NF) {
        sb1[threadIdx.x]       = re_b1[threadIdx.x];
        sbb[threadIdx.x]       = re_b2[threadIdx.x];
        sbb[64 + threadIdx.x]  = re_b3[threadIdx.x];
        sbb[128 + threadIdx.x] = rp_b[threadIdx.x];
    }
    __syncthreads();

    int e = blockIdx.x*128 + threadIdx.x;
    int node = e >> 3;
    int b = node / NN, i = node % NN;
    int j = g_send[e];
    int jj = j < 0 ? 0 : j;

    float rin[5];
    rin[0] = a_cur[b*NN + i];
    rin[1] = a_cur[b*NN + jj];
#pragma unroll
    for (int d = 0; d < 3; d++)
        rin[2+d] = states[((size_t)b*NN + i)*3 + d]
                 - states[((size_t)b*NN + jj)*3 + d];

    float h[64];
#pragma unroll
    for (int c4 = 0; c4 < 16; c4++) {
        float4 acc = *(const float4*)&sb1[c4*4];
#pragma unroll
        for (int r = 0; r < 5; r++) {
            float4 w = *(const float4*)&sw1[r*64 + c4*4];
            float x = rin[r];
            acc.x = fmaf(x, w.x, acc.x); acc.y = fmaf(x, w.y, acc.y);
            acc.z = fmaf(x, w.z, acc.z); acc.w = fmaf(x, w.w, acc.w);
        }
        h[c4*4+0] = fmaxf(acc.x, 0.f); h[c4*4+1] = fmaxf(acc.y, 0.f);
        h[c4*4+2] = fmaxf(acc.z, 0.f); h[c4*4+3] = fmaxf(acc.w, 0.f);
    }

    const float* wb = swb;
    const float* bb = sbb;
#pragma unroll 1
    for (int layer = 0; layer < 3; layer++) {
        unsigned long long acc2[32];
#pragma unroll
        for (int p = 0; p < 32; p++) PACK2(acc2[p], bb[2*p], bb[2*p+1]);
#pragma unroll
        for (int r = 0; r < 64; r++) {
            unsigned long long hd; DUP2(hd, h[r]);
#pragma unroll
            for (int c4 = 0; c4 < 16; c4++) {
                ulonglong2 w = *(const ulonglong2*)(wb + r*64 + c4*4);
                FMA2(acc2[c4*2],   w.x, hd);
                FMA2(acc2[c4*2+1], w.y, hd);
            }
        }
        if (layer < 2) {
#pragma unroll
            for (int p = 0; p < 32; p++) {
                float lo, hi; UNPK2(lo, hi, acc2[p]);
                h[2*p]   = fmaxf(lo, 0.f);
                h[2*p+1] = fmaxf(hi, 0.f);
            }
        } else {
            float* dst = g_A + (size_t)e*64;
#pragma unroll
            for (int c4 = 0; c4 < 16; c4++) {
                float x0,x1,x2,x3;
                UNPK2(x0, x1, acc2[c4*2]);
                UNPK2(x2, x3, acc2[c4*2+1]);
                *(float4*)(dst + c4*4) = make_float4(x0,x1,x2,x3);
            }
        }
        wb += 4096; bb += 64;
    }
}

// ---------------- K4a: UV = effin @ [Wr | Ws]  (register-blocked GEMM) ------
// grid = NNODES/32 = 128, 128 threads. Tile: 32 nodes x 128 cols.
// Thread: 4 nodes x 8 cols (FFMA2 over col pairs).
// sEd row = 64 duplicated floats (32 nodes as f32x2 pairs) -> stride 64.
#define SE 64
__global__ __launch_bounds__(128) void k_uv(
    int which, const float* __restrict__ rp_w)
{
    const float* effin = (which & 1) ? g_eff1 : g_eff0;
    extern __shared__ float dsm[];
    float* sW  = dsm;            // [64][128]
    float* sEd = dsm + 64*128;   // [64][SE] transposed + duplicated

    for (int t = threadIdx.x; t < 64*128; t += 128) {
        int r = t >> 7, c = t & 127;
        sW[t] = (c < 64) ? rp_w[(size_t)(64+r)*64 + c]
                         : rp_w[(size_t)(128+r)*64 + (c-64)];
    }
    int node0 = blockIdx.x * 32;
    {
        int n  = threadIdx.x >> 2;   // 0..31
        int cg = threadIdx.x & 3;    // 0..3 (16-col chunks)
        const float* src = effin + (size_t)(node0 + n)*64 + cg*16;
#pragma unroll
        for (int m4 = 0; m4 < 4; m4++) {
            float4 v = *(const float4*)(src + m4*4);
            int c = cg*16 + m4*4;
            *(float2*)&sEd[(c+0)*SE + 2*n] = make_float2(v.x, v.x);
            *(float2*)&sEd[(c+1)*SE + 2*n] = make_float2(v.y, v.y);
            *(float2*)&sEd[(c+2)*SE + 2*n] = make_float2(v.z, v.z);
            *(float2*)&sEd[(c+3)*SE + 2*n] = make_float2(v.w, v.w);
        }
    }
    __syncthreads();

    int tc = threadIdx.x & 15;   // 16 col-groups of 8
    int tn = threadIdx.x >> 4;   // 8 node-groups of 4
    unsigned long long acc[4][4];
#pragma unroll
    for (int m = 0; m < 4; m++)
#pragma unroll
        for (int p = 0; p < 4; p++) acc[m][p] = 0ULL;

#pragma unroll 4
    for (int r = 0; r < 64; r++) {
        unsigned long long ev[4];
#pragma unroll
        for (int m = 0; m < 4; m++)
            ev[m] = *(const unsigned long long*)&sEd[r*SE + tn*8 + 2*m];
        ulonglong2 w01 = *(const ulonglong2*)&sW[r*128 + tc*8];
        ulonglong2 w23 = *(const ulonglong2*)&sW[r*128 + tc*8 + 4];
#pragma unroll
        for (int m = 0; m < 4; m++) {
            FMA2(acc[m][0], w01.x, ev[m]);
            FMA2(acc[m][1], w01.y, ev[m]);
            FMA2(acc[m][2], w23.x, ev[m]);
            FMA2(acc[m][3], w23.y, ev[m]);
        }
    }
#pragma unroll
    for (int m = 0; m < 4; m++) {
        int node = node0 + tn*4 + m;
        float x0,x1,x2,x3,x4,x5,x6,x7;
        UNPK2(x0,x1, acc[m][0]); UNPK2(x2,x3, acc[m][1]);
        UNPK2(x4,x5, acc[m][2]); UNPK2(x6,x7, acc[m][3]);
        float* dst = g_UV + (size_t)node*128 + tc*8;
        *(float4*)dst       = make_float4(x0,x1,x2,x3);
        *(float4*)(dst + 4) = make_float4(x4,x5,x6,x7);
    }
}

// ---------------- K4b: edge pass + aggregate + output GEMM ------------------
// grid = NNODES/32 = 128, 256 threads.
// Phase1: warp per 4 nodes; lane = 2 channels. rel_eff = relu(A + U_i + V_j).
// Phase2: effout = relu(effin + q + agg @ Wp1), tile 32x64, thread 4n x 2c.
// sAgg row = 64 duplicated floats; stride 66 to break the 2l-row bank collision.
#define SA 66
__global__ __launch_bounds__(256) void k_edgeagg(
    int which, const float* __restrict__ pp_w)
{
    const float* effin  = (which & 1) ? g_eff1 : g_eff0;
    float*       effout = (which & 1) ? g_eff0 : g_eff1;
    extern __shared__ float dsm[];
    float* sWp  = dsm;          // [64][64] = pp_w rows 64..127
    float* sAgg = dsm + 4096;   // [64][SA] transposed + duplicated

    for (int t = threadIdx.x; t < 4096; t += 256) sWp[t] = pp_w[4096 + t];

    int w = threadIdx.x >> 5, l = threadIdx.x & 31;
    int node0 = blockIdx.x * 32;
#pragma unroll 1
    for (int kk = 0; kk < 4; kk++) {
        int node = node0 + w*4 + kk;
        int bN = (node >= NN) ? NN : 0;
        float2 u = *(const float2*)&g_UV[(size_t)node*128 + 2*l];
        float s0 = 0.f, s1 = 0.f;
#pragma unroll
        for (int k = 0; k < TK; k++) {
            int j = g_send[node*TK + k];       // warp-uniform
            if (j >= 0) {
                float2 a = *(const float2*)&g_A[((size_t)node*TK + k)*64 + 2*l];
                float2 v = *(const float2*)&g_UV[(size_t)(bN + j)*128 + 64 + 2*l];
                s0 += fmaxf(a.x + u.x + v.x, 0.f);
                s1 += fmaxf(a.y + u.y + v.y, 0.f);
            }
        }
        int nl = node - node0;
        *(float2*)&sAgg[(2*l  )*SA + 2*nl] = make_float2(s0, s0);
        *(float2*)&sAgg[(2*l+1)*SA + 2*nl] = make_float2(s1, s1);
    }
    __syncthreads();

    int tc = threadIdx.x & 31;   // 32 col-groups of 2
    int tn = threadIdx.x >> 5;   // 8 node-groups of 4
    unsigned long long acc[4] = {0ULL, 0ULL, 0ULL, 0ULL};
#pragma unroll 4
    for (int r = 0; r < 64; r++) {
        unsigned long long wv = *(const unsigned long long*)&sWp[r*64 + tc*2];
#pragma unroll
        for (int m = 0; m < 4; m++) {
            unsigned long long ev =
                *(const unsigned long long*)&sAgg[r*SA + tn*8 + 2*m];
            FMA2(acc[m], wv, ev);
        }
    }
#pragma unroll
    for (int m = 0; m < 4; m++) {
        int node = node0 + tn*4 + m;
        float2 ein = *(const float2*)&effin[(size_t)node*64 + 2*tc];
        float2 q2  = *(const float2*)&g_q  [(size_t)node*64 + 2*tc];
        float o0, o1; UNPK2(o0, o1, acc[m]);
        *(float2*)&effout[(size_t)node*64 + 2*tc] =
            make_float2(fmaxf(o0 + ein.x + q2.x, 0.f),
                        fmaxf(o1 + ein.y + q2.y, 0.f));
    }
}

// ---------------- K5: predictor + residual add ----------------
__global__ __launch_bounds__(256) void k_pred(
    const float* __restrict__ states,
    const float* __restrict__ pr_w1, const float* __restrict__ pr_b1,
    const float* __restrict__ pr_w2, const float* __restrict__ pr_b2,
    float* __restrict__ out)
{
    __shared__ float W1[NF*NF], b1[NF];
    __shared__ float W2[NF*3],  b2[3];
    __shared__ float ef[4][NF], hh[4][NF];
    for (int t = threadIdx.x; t < NF*NF; t += 256) W1[t] = pr_w1[t];
    for (int t = threadIdx.x; t < NF*3;  t += 256) W2[t] = pr_w2[t];
    if (threadIdx.x < NF) b1[threadIdx.x] = pr_b1[threadIdx.x];
    if (threadIdx.x < 3)  b2[threadIdx.x] = pr_b2[threadIdx.x];
    __syncthreads();

    int g = threadIdx.x >> 6;
    int c = threadIdx.x & 63;
    for (int it = 0; it < 4; ++it) {
        int node = blockIdx.x*16 + it*4 + g;
        ef[g][c] = g_eff1[(size_t)node*NF + c];
        __syncthreads();
        float acc = b1[c];
#pragma unroll 16
        for (int r = 0; r < NF; r++) acc = fmaf(ef[g][r], W1[r*NF+c], acc);
        hh[g][c] = fmaxf(acc, 0.f);
        __syncthreads();
        if (c < 3) {
            float p = b2[c];
#pragma unroll 16
            for (int r = 0; r < NF; r++) p = fmaf(hh[g][r], W2[r*3+c], p);
            out[(size_t)node*3 + c] = states[(size_t)node*3 + c] + p;
        }
        __syncthreads();
    }
}

// ---------------- launch ----------------
extern "C" void kernel_launch(void* const* d_in, const int* in_sizes, int n_in,
                              void* d_out, int out_size)
{
    const float* states  = (const float*)d_in[0];
    const float* a_cur   = (const float*)d_in[1];
    const float* s_delta = (const float*)d_in[2];
    const unsigned char* mask  = (const unsigned char*)d_in[3];
    const unsigned char* tmask = (const unsigned char*)d_in[4];
    int wbase = (n_in > 5 && in_sizes[5] == 1) ? 6 : 5;
    const float* pe_w1 = (const float*)d_in[wbase + 0];
    const float* pe_b1 = (const float*)d_in[wbase + 1];
    const float* pe_w2 = (const float*)d_in[wbase + 2];
    const float* pe_b2 = (const float*)d_in[wbase + 3];
    const float* re_w1 = (const float*)d_in[wbase + 4];
    const float* re_b1 = (const float*)d_in[wbase + 5];
    const float* re_w2 = (const float*)d_in[wbase + 6];
    const float* re_b2 = (const float*)d_in[wbase + 7];
    const float* re_w3 = (const float*)d_in[wbase + 8];
    const float* re_b3 = (const float*)d_in[wbase + 9];
    const float* rp_w  = (const float*)d_in[wbase + 10];
    const float* rp_b  = (const float*)d_in[wbase + 11];
    const float* pp_w  = (const float*)d_in[wbase + 12];
    const float* pp_b  = (const float*)d_in[wbase + 13];
    const float* pr_w1 = (const float*)d_in[wbase + 14];
    const float* pr_b1 = (const float*)d_in[wbase + 15];
    const float* pr_w2 = (const float*)d_in[wbase + 16];
    const float* pr_b2 = (const float*)d_in[wbase + 17];
    float* out = (float*)d_out;

    const int REL_SMEM = (320 + 3*4096 + 64 + 3*64) * 4;   // 51456 B
    const int UV_SMEM  = (64*128 + 64*SE) * 4;             // 49152 B
    const int AGG_SMEM = (4096 + 64*SA) * 4;               // 33280 B
    static int attr_done = 0;
    if (!attr_done) {
        cudaFuncSetAttribute(k_rel, cudaFuncAttributeMaxDynamicSharedMemorySize, REL_SMEM);
        cudaFuncSetAttribute(k_uv,  cudaFuncAttributeMaxDynamicSharedMemorySize, UV_SMEM);
        cudaFuncSetAttribute(k_edgeagg, cudaFuncAttributeMaxDynamicSharedMemorySize, AGG_SMEM);
        attr_done = 1;
    }

    k_masks<<<(NNODES + 255)/256, 256>>>(mask, tmask);
    k_edges<<<NNODES/8, 256>>>(states);
    k_penc <<<NNODES/16, 256>>>(s_delta, a_cur, pe_w1, pe_b1, pe_w2, pe_b2,
                                pp_w, pp_b);
    k_rel  <<<NE/128, 128, REL_SMEM>>>(states, a_cur,
                                       re_w1, re_b1, re_w2, re_b2,
                                       re_w3, re_b3, rp_w, rp_b);
    for (int s = 0; s < 3; s++) {
        k_uv     <<<NNODES/32, 128, UV_SMEM >>>(s, rp_w);
        k_edgeagg<<<NNODES/32, 256, AGG_SMEM>>>(s, pp_w);
    }
    k_pred <<<NNODES/16, 256>>>(states, pr_w1, pr_b1, pr_w2, pr_b2, out);
}